// round 14
// baseline (speedup 1.0000x reference)
#include <cuda_runtime.h>
#include <cuda_fp16.h>
#include <cstdint>

// ---------------------------------------------------------------------------
// BERTHeading, fully fused: merged 4-segment fp16 mma.sync GEMM with the
// per-sample epilogue (positional max, per-token L2 norm, transpose write,
// pooled word vector) executed INSIDE the GEMM kernel by the block that
// completes each sample's scratch (last-writer detection via atomic row
// counters; 114 = (20+19+18) rows x 2 n-halves per sample).
// GEMM core: round-10 proven config — 512 threads (16 warps, 64x32 warp
// tile), BM=128 x BN=256, K-chunk 32, 4-stage race-free cp.async pipeline.
// ---------------------------------------------------------------------------

#define BS      4096
#define EMB     768
#define FEAT    512

#define BM      128
#define BN      256
#define BKF     32                  // K elements per chunk
#define KPH     40                  // halves stride (80 B, ldmatrix conflict-free)
#define A_STG_B (BM * KPH * 2)      // 10240 B
#define B_STG_B (BN * KPH * 2)      // 20480 B
#define STG_B   (A_STG_B + B_STG_B) // 30720 B
#define STAGES  4
#define SMEM_TOTAL (STAGES * STG_B) // 122880 B (epilogue workspace aliases it)

#define ROWS_PER_SAMPLE 114         // (20+19+18) rows x 2 n-halves

__device__ __half g_Ah[BS * 20 * FEAT];
__device__ __half g_Bh[BS * 19 * FEAT];
__device__ __half g_Ch[BS * 18 * FEAT];
__device__ __half g_Xh[BS * 20 * EMB];     // fp16 words_emb
__device__ __half g_Sh[BS * EMB];          // fp16 sent_emb
// transposed fp16 weights, [512, K] row-major: W1 | W2 | W3 | Wp
__device__ __half g_Wth[512 * (768 + 1536 + 2304 + 768)];
__device__ int    g_cnt[BS];               // per-sample row counters (memset/launch)

struct Seg {
    const __half* X;
    const __half* Wt;
    const float*  bias;
    void*         Y;
    int K, T, srcStride, doRelu, outHalf, blkStart;
};
struct Params {
    Seg seg[4];
    float* words_out;
    float* word_vec;
};

struct TSeg { const float* W; __half* Wt; int K; int kbStart; };
struct TParams { TSeg seg[4]; };

#define CP_ASYNC16(saddr, gptr) \
    asm volatile("cp.async.cg.shared.global [%0], [%1], 16;" :: "r"(saddr), "l"(gptr))
#define CP_COMMIT() asm volatile("cp.async.commit_group;" ::: "memory")
#define CP_WAIT2()  asm volatile("cp.async.wait_group 2;" ::: "memory")

__device__ __forceinline__ uint32_t smem_u32(const void* p) {
    uint32_t a;
    asm("{ .reg .u64 t; cvta.to.shared.u64 t, %1; cvt.u32.u64 %0, t; }"
        : "=r"(a) : "l"(p));
    return a;
}

__device__ __forceinline__ void mma_f16(float* d, const uint32_t* a,
                                        const uint32_t* b) {
    asm volatile(
        "mma.sync.aligned.m16n8k16.row.col.f32.f16.f16.f32 "
        "{%0,%1,%2,%3}, {%4,%5,%6,%7}, {%8,%9}, {%0,%1,%2,%3};"
        : "+f"(d[0]), "+f"(d[1]), "+f"(d[2]), "+f"(d[3])
        : "r"(a[0]), "r"(a[1]), "r"(a[2]), "r"(a[3]), "r"(b[0]), "r"(b[1]));
}

__device__ __forceinline__ void ldsm_x4(uint32_t* r, uint32_t addr) {
    asm volatile(
        "ldmatrix.sync.aligned.m8n8.x4.shared.b16 {%0,%1,%2,%3}, [%4];"
        : "=r"(r[0]), "=r"(r[1]), "=r"(r[2]), "=r"(r[3]) : "r"(addr));
}

// L2-coherent half2 load (bypasses L1 — safe for cross-block scratch reads)
__device__ __forceinline__ float2 ldcg_h2f(const __half2* p) {
    uint32_t v;
    asm volatile("ld.global.cg.b32 %0, [%1];" : "=r"(v) : "l"(p));
    __half2 h = *reinterpret_cast<__half2*>(&v);
    return __half22float2(h);
}

// ---------------------------------------------------------------------------
// f32 -> f16 conversion, both inputs in one launch (i in float4 units)
// ---------------------------------------------------------------------------
__global__ void cvt_inputs(const float* __restrict__ words,
                           const float* __restrict__ sent)
{
    const int n4w = BS * 20 * EMB / 4;
    const int n4s = BS * EMB / 4;
    int i = blockIdx.x * blockDim.x + threadIdx.x;
    const float* src;
    __half2* dst;
    if (i < n4w) {
        src = words;  dst = (__half2*)g_Xh;
    } else if (i < n4w + n4s) {
        i -= n4w;  src = sent;  dst = (__half2*)g_Sh;
    } else return;
    float4 v = ((const float4*)src)[i];
    dst[2 * (size_t)i]     = __floats2half2_rn(v.x, v.y);
    dst[2 * (size_t)i + 1] = __floats2half2_rn(v.z, v.w);
}

// ---------------------------------------------------------------------------
// All 4 weight transposes in one launch: W [K,512] -> Wt [512,K] fp16
// blockIdx.x in kb-block units (32 K per block): 24 | 48 | 72 | 24 = 168
// ---------------------------------------------------------------------------
__global__ void transpose_all(TParams p)
{
    const int kbb = blockIdx.x;
    const int sid = (kbb >= p.seg[1].kbStart) + (kbb >= p.seg[2].kbStart)
                  + (kbb >= p.seg[3].kbStart);
    const TSeg sg = p.seg[sid];

    __shared__ float t[32][33];
    const int kb = (kbb - sg.kbStart) * 32, nb = blockIdx.y * 32;
    const int x = threadIdx.x, y = threadIdx.y;   // 32 x 8
    #pragma unroll
    for (int i = 0; i < 32; i += 8)
        t[y + i][x] = sg.W[(size_t)(kb + y + i) * FEAT + nb + x];
    __syncthreads();
    #pragma unroll
    for (int i = 0; i < 32; i += 8)
        sg.Wt[(size_t)(nb + y + i) * sg.K + kb + x] = __float2half_rn(t[x][y + i]);
}

// ---------------------------------------------------------------------------
// Per-sample epilogue, run by one GEMM block with all 512 threads.
// ws: smem workspace (aliases the GEMM pipeline stages; >= 44 KB used).
// Threads 0..255 each own feature pair (2u, 2u+1); all 512 join the
// coalesced write phase.
// ---------------------------------------------------------------------------
__device__ __forceinline__ void sample_epilogue(
    int s, char* ws, float* __restrict__ words_out,
    float* __restrict__ word_vec, int tid)
{
    float* scode = (float*)ws;              // 512*21 floats = 43008 B
    float* redp  = scode + 512 * 21;        // [21][8]
    float* invn  = redp + 21 * 8;           // 21 floats

    const int lane = tid & 31;
    const int w8   = (tid >> 5) & 7;
    const bool active = tid < 256;          // warps 0..7 fully active

    float code0[20], code1[20];
    float pooled0 = 0.0f, pooled1 = 0.0f;

    if (active) {
        const int u = tid;
        const __half2* Ab = (const __half2*)(g_Ah + (size_t)s * 20 * FEAT) + u;
        const __half2* Bb = (const __half2*)(g_Bh + (size_t)s * 19 * FEAT) + u;
        const __half2* Cb = (const __half2*)(g_Ch + (size_t)s * 18 * FEAT) + u;
        const int H = FEAT / 2;

        float ma0 = 0.f, mb0 = 0.f, mc0 = 0.f;
        float ma1 = 0.f, mb1 = 0.f, mc1 = 0.f;
        #pragma unroll
        for (int t = 0; t < 20; t++) {
            float2 av = ldcg_h2f(Ab + t * H);
            float2 bv = (t < 19) ? ldcg_h2f(Bb + t * H) : make_float2(0.f, 0.f);
            float2 cv = (t < 18) ? ldcg_h2f(Cb + t * H) : make_float2(0.f, 0.f);
            ma0 = fmaxf(ma0, av.x);  ma1 = fmaxf(ma1, av.y);
            mb0 = fmaxf(mb0, bv.x);  mb1 = fmaxf(mb1, bv.y);
            mc0 = fmaxf(mc0, cv.x);  mc1 = fmaxf(mc1, cv.y);
            float cd0 = fmaxf(av.x, fmaxf(bv.x, cv.x));
            float cd1 = fmaxf(av.y, fmaxf(bv.y, cv.y));
            code0[t] = cd0;
            code1[t] = cd1;
            float ss = cd0 * cd0 + cd1 * cd1;
            #pragma unroll
            for (int o = 16; o > 0; o >>= 1)
                ss += __shfl_xor_sync(0xffffffffu, ss, o);
            if (lane == 0) redp[t * 8 + w8] = ss;
        }
        pooled0 = (ma0 + mb0 + mc0) * (1.0f / 3.0f);
        pooled1 = (ma1 + mb1 + mc1) * (1.0f / 3.0f);
        float ps = pooled0 * pooled0 + pooled1 * pooled1;
        #pragma unroll
        for (int o = 16; o > 0; o >>= 1)
            ps += __shfl_xor_sync(0xffffffffu, ps, o);
        if (lane == 0) redp[20 * 8 + w8] = ps;
    }
    __syncthreads();

    if (tid < 21) {
        float ssum = 0.0f;
        #pragma unroll
        for (int i = 0; i < 8; i++) ssum += redp[tid * 8 + i];
        invn[tid] = 1.0f / fmaxf(sqrtf(ssum), 1e-12f);
    }
    __syncthreads();

    if (active) {
        float* s0 = &scode[(2 * tid) * 21];
        float* s1 = s0 + 21;
        #pragma unroll
        for (int t = 0; t < 20; t++) {
            const float iv = invn[t];
            s0[t] = code0[t] * iv;
            s1[t] = code1[t] * iv;
        }
    }
    __syncthreads();

    // coalesced words_out write: 512*20 floats = 2560 float4 / 512 thr = 5
    float* op = words_out + (size_t)s * FEAT * 20;
    #pragma unroll
    for (int q = 0; q < 5; q++) {
        const int g = (q * 512 + tid) * 4;
        float4 v;
        #pragma unroll
        for (int e = 0; e < 4; e++) {
            const int gi = g + e;
            const int cc = gi / 20;
            const int tt = gi - cc * 20;
            ((float*)&v)[e] = scode[cc * 21 + tt];
        }
        *(float4*)(op + g) = v;
    }

    if (active) {
        const float ivp = invn[20];
        *(float2*)(word_vec + (size_t)s * FEAT + 2 * tid) =
            make_float2(pooled0 * ivp, pooled1 * ivp);
    }
}

// ---------------------------------------------------------------------------
// Merged fp16 mma.sync GEMM (4 segments) + fused last-writer epilogue.
// ---------------------------------------------------------------------------
__global__ void __launch_bounds__(512, 1)
gemm_f16(Params p)
{
    extern __shared__ char smem[];
    const int bid = blockIdx.x;
    const int sid = (bid >= p.seg[1].blkStart) + (bid >= p.seg[2].blkStart)
                  + (bid >= p.seg[3].blkStart);
    const Seg sg = p.seg[sid];

    const int idx = bid - sg.blkStart;
    const int mb  = idx >> 1;          // m-tile
    const int nb  = (idx & 1) * BN;    // n offset (FEAT/BN == 2)

    const int tid  = threadIdx.x;
    const int lane = tid & 31;
    const int wid  = tid >> 5;         // 0..15
    const int wm   = wid & 1;          // 2 m-warps (64 rows each)
    const int wn   = wid >> 1;         // 8 n-warps (32 cols each)
    const int r    = lane >> 2;        // 0..7
    const int cq   = lane & 3;         // 0..3

    const uint32_t sbase = smem_u32(smem);

    // ---- loader addresses (512 threads) ----
    const int am = mb * BM + (tid >> 2);
    const __half* aRow = sg.X + (size_t)(am / sg.T) * sg.srcStride
                              + (size_t)(am % sg.T) * EMB + (tid & 3) * 8;
    const uint32_t aDst = sbase + ((tid >> 2) * KPH + (tid & 3) * 8) * 2;
    const __half* bRow = sg.Wt + (size_t)(nb + (tid >> 1)) * sg.K + (tid & 1) * 16;
    const uint32_t bDst = sbase + A_STG_B
                        + ((tid >> 1) * KPH + (tid & 1) * 16) * 2;

    const int Kc = sg.K / BKF;

    auto load_chunk = [&](int chunk) {
        const uint32_t so = (uint32_t)((chunk & (STAGES - 1)) * STG_B);
        const int kc = chunk * BKF;
        CP_ASYNC16(aDst + so, aRow + kc);
        CP_ASYNC16(bDst + so,      bRow + kc);
        CP_ASYNC16(bDst + so + 16, bRow + kc + 8);
    };

    float acc[4][4][4];
    #pragma unroll
    for (int mi = 0; mi < 4; mi++)
        #pragma unroll
        for (int nj = 0; nj < 4; nj++)
            #pragma unroll
            for (int q = 0; q < 4; q++) acc[mi][nj][q] = 0.0f;

    load_chunk(0); CP_COMMIT();
    load_chunk(1); CP_COMMIT();
    load_chunk(2); CP_COMMIT();

    const int rowOff = ((lane >> 3) & 1) * 8 + (lane & 7);
    const int khOff  = (lane >> 4) * 8;
    const uint32_t aFragBase =
        sbase + ((wm * 64 + rowOff) * KPH + khOff) * 2;
    const uint32_t bFragBase =
        sbase + A_STG_B + ((wn * 32 + rowOff) * KPH + khOff) * 2;

    for (int c = 0; c < Kc; c++) {
        CP_WAIT2();                      // own cp.asyncs for chunk c landed
        __syncthreads();                 // everyone's chunk c landed; c-1 read
        if (c + 3 < Kc) load_chunk(c + 3);
        CP_COMMIT();

        const uint32_t so = (uint32_t)((c & (STAGES - 1)) * STG_B);

        #pragma unroll
        for (int ks = 0; ks < 2; ks++) {
            uint32_t af[4][4];
            #pragma unroll
            for (int mi = 0; mi < 4; mi++)
                ldsm_x4(af[mi], aFragBase + so + (mi * 16 * KPH + ks * 16) * 2);
            uint32_t bf[2][4];
            #pragma unroll
            for (int njp = 0; njp < 2; njp++)
                ldsm_x4(bf[njp], bFragBase + so + (njp * 16 * KPH + ks * 16) * 2);

            #pragma unroll
            for (int mi = 0; mi < 4; mi++)
                #pragma unroll
                for (int njp = 0; njp < 2; njp++) {
                    uint32_t b0[2] = { bf[njp][0], bf[njp][2] };
                    uint32_t b1[2] = { bf[njp][1], bf[njp][3] };
                    mma_f16(acc[mi][2 * njp + 0], af[mi], b0);
                    mma_f16(acc[mi][2 * njp + 1], af[mi], b1);
                }
        }
    }

    // ---- GEMM epilogue: bias (+relu), write Y ----
    const int mBase = mb * BM + wm * 64 + r;
    const int nBase = nb + wn * 32 + cq * 2;
    float bb[4][2];
    #pragma unroll
    for (int nj = 0; nj < 4; nj++) {
        bb[nj][0] = __ldg(sg.bias + nBase + nj * 8);
        bb[nj][1] = __ldg(sg.bias + nBase + nj * 8 + 1);
    }
    #pragma unroll
    for (int mi = 0; mi < 4; mi++) {
        #pragma unroll
        for (int rr = 0; rr < 2; rr++) {
            const size_t rowOffY = (size_t)(mBase + mi * 16 + rr * 8) * FEAT;
            #pragma unroll
            for (int nj = 0; nj < 4; nj++) {
                float v0 = acc[mi][nj][rr * 2 + 0] + bb[nj][0];
                float v1 = acc[mi][nj][rr * 2 + 1] + bb[nj][1];
                if (sg.doRelu) { v0 = fmaxf(v0, 0.0f); v1 = fmaxf(v1, 0.0f); }
                if (sg.outHalf) {
                    __half2* yh = (__half2*)((__half*)sg.Y + rowOffY + nBase + nj * 8);
                    *yh = __floats2half2_rn(v0, v1);
                } else {
                    float* yf = (float*)sg.Y + rowOffY + nBase + nj * 8;
                    *(float2*)yf = make_float2(v0, v1);
                }
            }
        }
    }

    // ---- fused per-sample epilogue (conv segments only) ----
    if (sg.outHalf) {
        __threadfence();                 // each thread: publish its stores
        __shared__ int s_todo[8];
        __shared__ int s_n;
        __syncthreads();                 // all stores + fences done

        if (tid == 0) {
            int n = 0;
            const int rlo = mb * BM, rhi = rlo + BM;
            const int sFirst = rlo / sg.T;
            const int sLast  = (rhi - 1) / sg.T;
            for (int ss = sFirst; ss <= sLast; ss++) {
                int lo = ss * sg.T, hi = lo + sg.T;
                if (lo < rlo) lo = rlo;
                if (hi > rhi) hi = rhi;
                const int contrib = hi - lo;
                const int old = atomicAdd(&g_cnt[ss], contrib);
                if (old + contrib == ROWS_PER_SAMPLE)
                    s_todo[n++] = ss;
            }
            s_n = n;
        }
        __syncthreads();
        __threadfence();                 // acquire side (reads are .cg anyway)

        const int n = s_n;
        for (int i = 0; i < n; i++) {
            sample_epilogue(s_todo[i], smem, p.words_out, p.word_vec, tid);
            __syncthreads();             // scode reuse across samples
        }
    }
}

// ---------------------------------------------------------------------------
extern "C" void kernel_launch(void* const* d_in, const int* in_sizes, int n_in,
                              void* d_out, int out_size)
{
    const float* words = (const float*)d_in[0];
    const float* sentE = (const float*)d_in[1];
    const float* W1 = (const float*)d_in[2];
    const float* b1 = (const float*)d_in[3];
    const float* W2 = (const float*)d_in[4];
    const float* b2 = (const float*)d_in[5];
    const float* W3 = (const float*)d_in[6];
    const float* b3 = (const float*)d_in[7];
    const float* Wp = (const float*)d_in[8];
    const float* bp = (const float*)d_in[9];

    float* out       = (float*)d_out;
    float* words_out = out;
    float* word_vec  = out + (size_t)BS * FEAT * 20;
    float* sent_out  = word_vec + (size_t)BS * FEAT;

    cudaFuncSetAttribute(gemm_f16, cudaFuncAttributeMaxDynamicSharedMemorySize,
                         SMEM_TOTAL);

    __half *xh, *sh, *wth, *gA, *gB, *gC;
    int* cnt;
    cudaGetSymbolAddress((void**)&xh,  g_Xh);
    cudaGetSymbolAddress((void**)&sh,  g_Sh);
    cudaGetSymbolAddress((void**)&wth, g_Wth);
    cudaGetSymbolAddress((void**)&gA,  g_Ah);
    cudaGetSymbolAddress((void**)&gB,  g_Bh);
    cudaGetSymbolAddress((void**)&gC,  g_Ch);
    cudaGetSymbolAddress((void**)&cnt, g_cnt);
    __half* wt1 = wth;
    __half* wt2 = wt1 + (size_t)512 * 768;
    __half* wt3 = wt2 + (size_t)512 * 1536;
    __half* wtp = wt3 + (size_t)512 * 2304;

    // zero the per-sample counters (every launch / graph replay)
    cudaMemsetAsync(cnt, 0, BS * sizeof(int));

    // input conversions (one launch)
    {
        int n4 = BS * 20 * EMB / 4 + BS * EMB / 4;
        cvt_inputs<<<(n4 + 255) / 256, 256>>>(words, sentE);
    }
    // weight transposes (one launch): kb blocks 24 | 48 | 72 | 24
    {
        TParams tp;
        tp.seg[0] = { W1, wt1, 768,  0 };
        tp.seg[1] = { W2, wt2, 1536, 24 };
        tp.seg[2] = { W3, wt3, 2304, 72 };
        tp.seg[3] = { Wp, wtp, 768,  144 };
        transpose_all<<<dim3(168, 16), dim3(32, 8)>>>(tp);
    }

    const int SSTRIDE = 20 * EMB;   // 15360

    // Merged GEMM + fused epilogue: longest-K segments first
    Params p;
    // conv3: M=73728 -> 576 mb x 2 = 1152 blocks
    p.seg[0] = { xh, wt3, b3, gC,       2304, 18, SSTRIDE, 1, 1, 0 };
    // conv2: M=77824 -> 608 x 2 = 1216
    p.seg[1] = { xh, wt2, b2, gB,       1536, 19, SSTRIDE, 1, 1, 1152 };
    // conv1: M=81920 -> 640 x 2 = 1280
    p.seg[2] = { xh, wt1, b1, gA,        768, 20, SSTRIDE, 1, 1, 2368 };
    // sent:  M=4096  -> 32 x 2 = 64 (f32 external output, no fused epilogue)
    p.seg[3] = { sh, wtp, bp, sent_out,  768,  1, EMB,     0, 0, 3648 };
    p.words_out = words_out;
    p.word_vec  = word_vec;

    gemm_f16<<<3712, 512, SMEM_TOTAL>>>(p);
}

// round 15
// speedup vs baseline: 1.0752x; 1.0752x over previous
#include <cuda_runtime.h>
#include <cuda_fp16.h>
#include <cstdint>

// ---------------------------------------------------------------------------
// BERTHeading via warp-level mma.sync fp16 GEMMs (f32 accumulate).
// GEMM: round-10/13 proven config — merged 4-segment launch, 512 threads/CTA
// (16 warps, 64x32 warp tile), BM=128 x BN=256, K-chunk 32, 4-stage cp.async
// pipeline (race-free: wait_group 2 -> barrier -> prefetch(c+3) -> compute).
// fp16 scratch conv outputs. Separate epilogue kernel (2 samples/block,
// __half2 paired loads, coalesced writes). MLP-4 grid-stride input convert.
// ---------------------------------------------------------------------------

#define BS      4096
#define EMB     768
#define FEAT    512

#define BM      128
#define BN      256
#define BKF     32                  // K elements per chunk
#define KPH     40                  // halves stride (80 B, ldmatrix conflict-free)
#define A_STG_B (BM * KPH * 2)      // 10240 B
#define B_STG_B (BN * KPH * 2)      // 20480 B
#define STG_B   (A_STG_B + B_STG_B) // 30720 B
#define STAGES  4
#define SMEM_TOTAL (STAGES * STG_B) // 122880 B

__device__ __half g_Ah[BS * 20 * FEAT];
__device__ __half g_Bh[BS * 19 * FEAT];
__device__ __half g_Ch[BS * 18 * FEAT];
__device__ __half g_Xh[BS * 20 * EMB];     // fp16 words_emb
__device__ __half g_Sh[BS * EMB];          // fp16 sent_emb
// transposed fp16 weights, [512, K] row-major: W1 | W2 | W3 | Wp
__device__ __half g_Wth[512 * (768 + 1536 + 2304 + 768)];

struct Seg {
    const __half* X;
    const __half* Wt;
    const float*  bias;
    void*         Y;
    int K, T, srcStride, doRelu, outHalf, blkStart;
};
struct Params { Seg seg[4]; };

struct TSeg { const float* W; __half* Wt; int K; int kbStart; };
struct TParams { TSeg seg[4]; };

#define CP_ASYNC16(saddr, gptr) \
    asm volatile("cp.async.cg.shared.global [%0], [%1], 16;" :: "r"(saddr), "l"(gptr))
#define CP_COMMIT() asm volatile("cp.async.commit_group;" ::: "memory")
#define CP_WAIT2()  asm volatile("cp.async.wait_group 2;" ::: "memory")

__device__ __forceinline__ uint32_t smem_u32(const void* p) {
    uint32_t a;
    asm("{ .reg .u64 t; cvta.to.shared.u64 t, %1; cvt.u32.u64 %0, t; }"
        : "=r"(a) : "l"(p));
    return a;
}

__device__ __forceinline__ void mma_f16(float* d, const uint32_t* a,
                                        const uint32_t* b) {
    asm volatile(
        "mma.sync.aligned.m16n8k16.row.col.f32.f16.f16.f32 "
        "{%0,%1,%2,%3}, {%4,%5,%6,%7}, {%8,%9}, {%0,%1,%2,%3};"
        : "+f"(d[0]), "+f"(d[1]), "+f"(d[2]), "+f"(d[3])
        : "r"(a[0]), "r"(a[1]), "r"(a[2]), "r"(a[3]), "r"(b[0]), "r"(b[1]));
}

__device__ __forceinline__ void ldsm_x4(uint32_t* r, uint32_t addr) {
    asm volatile(
        "ldmatrix.sync.aligned.m8n8.x4.shared.b16 {%0,%1,%2,%3}, [%4];"
        : "=r"(r[0]), "=r"(r[1]), "=r"(r[2]), "=r"(r[3]) : "r"(addr));
}

// ---------------------------------------------------------------------------
// f32 -> f16 conversion: grid-stride, 4 independent float4s in flight (MLP=4)
// ---------------------------------------------------------------------------
__device__ __forceinline__ void cvt_span(const float* __restrict__ src,
                                         __half2* __restrict__ dst,
                                         int n4, int i0, int gs)
{
    int i = i0;
    for (; i + 3 * gs < n4; i += 4 * gs) {
        float4 v0 = ((const float4*)src)[i];
        float4 v1 = ((const float4*)src)[i + gs];
        float4 v2 = ((const float4*)src)[i + 2 * gs];
        float4 v3 = ((const float4*)src)[i + 3 * gs];
        dst[2 * (size_t)i]                 = __floats2half2_rn(v0.x, v0.y);
        dst[2 * (size_t)i + 1]             = __floats2half2_rn(v0.z, v0.w);
        dst[2 * (size_t)(i + gs)]          = __floats2half2_rn(v1.x, v1.y);
        dst[2 * (size_t)(i + gs) + 1]      = __floats2half2_rn(v1.z, v1.w);
        dst[2 * (size_t)(i + 2 * gs)]      = __floats2half2_rn(v2.x, v2.y);
        dst[2 * (size_t)(i + 2 * gs) + 1]  = __floats2half2_rn(v2.z, v2.w);
        dst[2 * (size_t)(i + 3 * gs)]      = __floats2half2_rn(v3.x, v3.y);
        dst[2 * (size_t)(i + 3 * gs) + 1]  = __floats2half2_rn(v3.z, v3.w);
    }
    for (; i < n4; i += gs) {
        float4 v = ((const float4*)src)[i];
        dst[2 * (size_t)i]     = __floats2half2_rn(v.x, v.y);
        dst[2 * (size_t)i + 1] = __floats2half2_rn(v.z, v.w);
    }
}

__global__ void cvt_inputs(const float* __restrict__ words,
                           const float* __restrict__ sent)
{
    const int gs = gridDim.x * blockDim.x;
    const int i0 = blockIdx.x * blockDim.x + threadIdx.x;
    cvt_span(words, (__half2*)g_Xh, BS * 20 * EMB / 4, i0, gs);
    cvt_span(sent,  (__half2*)g_Sh, BS * EMB / 4,      i0, gs);
}

// ---------------------------------------------------------------------------
// All 4 weight transposes in one launch: W [K,512] -> Wt [512,K] fp16
// blockIdx.x in kb-block units (32 K per block): 24 | 48 | 72 | 24 = 168
// ---------------------------------------------------------------------------
__global__ void transpose_all(TParams p)
{
    const int kbb = blockIdx.x;
    const int sid = (kbb >= p.seg[1].kbStart) + (kbb >= p.seg[2].kbStart)
                  + (kbb >= p.seg[3].kbStart);
    const TSeg sg = p.seg[sid];

    __shared__ float t[32][33];
    const int kb = (kbb - sg.kbStart) * 32, nb = blockIdx.y * 32;
    const int x = threadIdx.x, y = threadIdx.y;   // 32 x 8
    #pragma unroll
    for (int i = 0; i < 32; i += 8)
        t[y + i][x] = sg.W[(size_t)(kb + y + i) * FEAT + nb + x];
    __syncthreads();
    #pragma unroll
    for (int i = 0; i < 32; i += 8)
        sg.Wt[(size_t)(nb + y + i) * sg.K + kb + x] = __float2half_rn(t[x][y + i]);
}

// ---------------------------------------------------------------------------
// Merged fp16 mma.sync GEMM (4 segments in one grid).
//   Y[m, nb..nb+255] = act( A(m,:) @ Wt[nb..nb+255,:]^T + bias )
//   A(m,:) = X + (m/T)*srcStride + (m%T)*768, contiguous K halves.
// 512 threads: 16 warps, 2 m-warps x 8 n-warps, 64x32 warp tile.
// ---------------------------------------------------------------------------
__global__ void __launch_bounds__(512, 1)
gemm_f16(Params p)
{
    extern __shared__ char smem[];
    const int bid = blockIdx.x;
    const int sid = (bid >= p.seg[1].blkStart) + (bid >= p.seg[2].blkStart)
                  + (bid >= p.seg[3].blkStart);
    const Seg sg = p.seg[sid];

    const int idx = bid - sg.blkStart;
    const int mb  = idx >> 1;          // m-tile
    const int nb  = (idx & 1) * BN;    // n offset (FEAT/BN == 2)

    const int tid  = threadIdx.x;
    const int lane = tid & 31;
    const int wid  = tid >> 5;         // 0..15
    const int wm   = wid & 1;          // 2 m-warps (64 rows each)
    const int wn   = wid >> 1;         // 8 n-warps (32 cols each)
    const int r    = lane >> 2;        // 0..7
    const int cq   = lane & 3;         // 0..3

    const uint32_t sbase = smem_u32(smem);

    // ---- loader addresses (512 threads) ----
    // A: 128 rows x 64 B; thread t -> row t/4, 16B chunk t%4 (1 cp.async)
    const int am = mb * BM + (tid >> 2);
    const __half* aRow = sg.X + (size_t)(am / sg.T) * sg.srcStride
                              + (size_t)(am % sg.T) * EMB + (tid & 3) * 8;
    const uint32_t aDst = sbase + ((tid >> 2) * KPH + (tid & 3) * 8) * 2;
    // B: 256 rows x 64 B; thread t -> row t/2, 32 B half (2 cp.async of 16 B)
    const __half* bRow = sg.Wt + (size_t)(nb + (tid >> 1)) * sg.K + (tid & 1) * 16;
    const uint32_t bDst = sbase + A_STG_B
                        + ((tid >> 1) * KPH + (tid & 1) * 16) * 2;

    const int Kc = sg.K / BKF;

    auto load_chunk = [&](int chunk) {
        const uint32_t so = (uint32_t)((chunk & (STAGES - 1)) * STG_B);
        const int kc = chunk * BKF;
        CP_ASYNC16(aDst + so, aRow + kc);
        CP_ASYNC16(bDst + so,      bRow + kc);       // bytes [x*32, x*32+16)
        CP_ASYNC16(bDst + so + 16, bRow + kc + 8);   // bytes [x*32+16, x*32+32)
    };

    float acc[4][4][4];
    #pragma unroll
    for (int mi = 0; mi < 4; mi++)
        #pragma unroll
        for (int nj = 0; nj < 4; nj++)
            #pragma unroll
            for (int q = 0; q < 4; q++) acc[mi][nj][q] = 0.0f;

    load_chunk(0); CP_COMMIT();
    load_chunk(1); CP_COMMIT();
    load_chunk(2); CP_COMMIT();

    // ldmatrix.x4 lane mapping: matrices {rows0-7@k0, rows8-15@k0,
    // rows0-7@k8, rows8-15@k8} of a 16x16-half block.
    const int rowOff = ((lane >> 3) & 1) * 8 + (lane & 7);
    const int khOff  = (lane >> 4) * 8;
    const uint32_t aFragBase =
        sbase + ((wm * 64 + rowOff) * KPH + khOff) * 2;
    const uint32_t bFragBase =
        sbase + A_STG_B + ((wn * 32 + rowOff) * KPH + khOff) * 2;

    for (int c = 0; c < Kc; c++) {
        // Race-free protocol:
        CP_WAIT2();                      // own cp.asyncs for chunk c landed
        __syncthreads();                 // => everyone's chunk c landed, and
                                         //    all warps finished reading c-1
        if (c + 3 < Kc) load_chunk(c + 3);   // overwrites stage of c-1: safe
        CP_COMMIT();                     // (possibly empty group; keeps count)

        const uint32_t so = (uint32_t)((c & (STAGES - 1)) * STG_B);

        #pragma unroll
        for (int ks = 0; ks < 2; ks++) {       // two k16 steps per 32-chunk
            uint32_t af[4][4];
            #pragma unroll
            for (int mi = 0; mi < 4; mi++)
                ldsm_x4(af[mi], aFragBase + so + (mi * 16 * KPH + ks * 16) * 2);
            uint32_t bf[2][4];   // [njp]: {nEven.b0, nOdd.b0, nEven.b1, nOdd.b1}
            #pragma unroll
            for (int njp = 0; njp < 2; njp++)
                ldsm_x4(bf[njp], bFragBase + so + (njp * 16 * KPH + ks * 16) * 2);

            #pragma unroll
            for (int mi = 0; mi < 4; mi++)
                #pragma unroll
                for (int njp = 0; njp < 2; njp++) {
                    uint32_t b0[2] = { bf[njp][0], bf[njp][2] };
                    uint32_t b1[2] = { bf[njp][1], bf[njp][3] };
                    mma_f16(acc[mi][2 * njp + 0], af[mi], b0);
                    mma_f16(acc[mi][2 * njp + 1], af[mi], b1);
                }
        }
    }

    // ---- epilogue: bias (+relu), write Y (fp16 scratch or f32 external) ----
    const int mBase = mb * BM + wm * 64 + r;
    const int nBase = nb + wn * 32 + cq * 2;
    float bb[4][2];
    #pragma unroll
    for (int nj = 0; nj < 4; nj++) {
        bb[nj][0] = __ldg(sg.bias + nBase + nj * 8);
        bb[nj][1] = __ldg(sg.bias + nBase + nj * 8 + 1);
    }
    #pragma unroll
    for (int mi = 0; mi < 4; mi++) {
        #pragma unroll
        for (int rr = 0; rr < 2; rr++) {
            const size_t rowOffY = (size_t)(mBase + mi * 16 + rr * 8) * FEAT;
            #pragma unroll
            for (int nj = 0; nj < 4; nj++) {
                float v0 = acc[mi][nj][rr * 2 + 0] + bb[nj][0];
                float v1 = acc[mi][nj][rr * 2 + 1] + bb[nj][1];
                if (sg.doRelu) { v0 = fmaxf(v0, 0.0f); v1 = fmaxf(v1, 0.0f); }
                if (sg.outHalf) {
                    __half2* yh = (__half2*)((__half*)sg.Y + rowOffY + nBase + nj * 8);
                    *yh = __floats2half2_rn(v0, v1);
                } else {
                    float* yf = (float*)sg.Y + rowOffY + nBase + nj * 8;
                    *(float2*)yf = make_float2(v0, v1);
                }
            }
        }
    }
}

// ---------------------------------------------------------------------------
// Epilogue: 2 samples per 512-thread block. Thread (sloc = tid>>8, u = tid&255)
// owns feature pair (2u, 2u+1) of sample s = 2*bid + sloc, loading __half2
// (full 128B line per warp). Per-token L2 norms via 8-warp/sample reduction;
// normalized values staged in f32 smem (stride 21), then both samples'
// words_out blocks written fully coalesced.
// ---------------------------------------------------------------------------
__global__ void __launch_bounds__(512)
epilogue_kernel(float* __restrict__ words_out, float* __restrict__ word_vec)
{
    const int tid  = threadIdx.x;
    const int sloc = tid >> 8;          // 0..1 : sample within block
    const int u    = tid & 255;         // feature pair index
    const int lane = tid & 31;
    const int wid  = tid >> 5;          // 0..15
    const int w8   = wid & 7;           // warp within sample

    const int s = 2 * blockIdx.x + sloc;

    __shared__ float scode[2][512 * 21];   // 86016 B
    __shared__ float red[2][21][8];
    __shared__ float invn[2][21];

    const __half2* Ab = (const __half2*)(g_Ah + (size_t)s * 20 * FEAT) + u;
    const __half2* Bb = (const __half2*)(g_Bh + (size_t)s * 19 * FEAT) + u;
    const __half2* Cb = (const __half2*)(g_Ch + (size_t)s * 18 * FEAT) + u;

    float code0[20], code1[20];
    float ma0 = 0.0f, mb0 = 0.0f, mc0 = 0.0f;
    float ma1 = 0.0f, mb1 = 0.0f, mc1 = 0.0f;
    const int H = FEAT / 2;   // 256 half2 per row

    #pragma unroll
    for (int t = 0; t < 20; t++) {
        float2 av = __half22float2(Ab[t * H]);
        float2 bv = (t < 19) ? __half22float2(Bb[t * H]) : make_float2(0.f, 0.f);
        float2 cv = (t < 18) ? __half22float2(Cb[t * H]) : make_float2(0.f, 0.f);
        ma0 = fmaxf(ma0, av.x);  ma1 = fmaxf(ma1, av.y);
        mb0 = fmaxf(mb0, bv.x);  mb1 = fmaxf(mb1, bv.y);
        mc0 = fmaxf(mc0, cv.x);  mc1 = fmaxf(mc1, cv.y);
        float cd0 = fmaxf(av.x, fmaxf(bv.x, cv.x));
        float cd1 = fmaxf(av.y, fmaxf(bv.y, cv.y));
        code0[t] = cd0;
        code1[t] = cd1;
        float ss = cd0 * cd0 + cd1 * cd1;
        #pragma unroll
        for (int o = 16; o > 0; o >>= 1) ss += __shfl_xor_sync(0xffffffffu, ss, o);
        if (lane == 0) red[sloc][t][w8] = ss;
    }

    float pooled0 = (ma0 + mb0 + mc0) * (1.0f / 3.0f);
    float pooled1 = (ma1 + mb1 + mc1) * (1.0f / 3.0f);
    {
        float ps = pooled0 * pooled0 + pooled1 * pooled1;
        #pragma unroll
        for (int o = 16; o > 0; o >>= 1) ps += __shfl_xor_sync(0xffffffffu, ps, o);
        if (lane == 0) red[sloc][20][w8] = ps;
    }
    __syncthreads();

    if (tid < 42) {                       // 2 samples x 21 norms
        const int sl = tid / 21, c = tid % 21;
        float ssum = 0.0f;
        #pragma unroll
        for (int i = 0; i < 8; i++) ssum += red[sl][c][i];
        invn[sl][c] = 1.0f / fmaxf(sqrtf(ssum), 1e-12f);
    }
    __syncthreads();

    // stage normalized values: feature c at scode[sloc][c*21 + t]
    {
        float* s0 = &scode[sloc][(2 * u) * 21];
        float* s1 = s0 + 21;
        #pragma unroll
        for (int t = 0; t < 20; t++) {
            const float iv = invn[sloc][t];
            s0[t] = code0[t] * iv;
            s1[t] = code1[t] * iv;
        }
    }
    __syncthreads();

    // coalesced words_out write: the 2 samples' blocks are contiguous:
    // 2 * 512 * 20 floats = 5120 float4 / 512 threads = 10 each.
    float* op = words_out + (size_t)blockIdx.x * 2 * FEAT * 20;
    #pragma unroll
    for (int q = 0; q < 10; q++) {
        const int g = (q * 512 + tid) * 4;       // float index in 2-sample blk
        const int so = g / (FEAT * 20);          // 0..1
        const int w  = g - so * FEAT * 20;
        float4 v;
        #pragma unroll
        for (int e = 0; e < 4; e++) {
            const int gi = w + e;
            const int cc = gi / 20;
            const int tt = gi - cc * 20;
            ((float*)&v)[e] = scode[so][cc * 21 + tt];
        }
        *(float4*)(op + g) = v;
    }

    const float ivp = invn[sloc][20];
    *(float2*)(word_vec + (size_t)s * FEAT + 2 * u) =
        make_float2(pooled0 * ivp, pooled1 * ivp);
}

// ---------------------------------------------------------------------------
extern "C" void kernel_launch(void* const* d_in, const int* in_sizes, int n_in,
                              void* d_out, int out_size)
{
    const float* words = (const float*)d_in[0];
    const float* sentE = (const float*)d_in[1];
    const float* W1 = (const float*)d_in[2];
    const float* b1 = (const float*)d_in[3];
    const float* W2 = (const float*)d_in[4];
    const float* b2 = (const float*)d_in[5];
    const float* W3 = (const float*)d_in[6];
    const float* b3 = (const float*)d_in[7];
    const float* Wp = (const float*)d_in[8];
    const float* bp = (const float*)d_in[9];

    float* out       = (float*)d_out;
    float* words_out = out;
    float* word_vec  = out + (size_t)BS * FEAT * 20;
    float* sent_out  = word_vec + (size_t)BS * FEAT;

    cudaFuncSetAttribute(gemm_f16, cudaFuncAttributeMaxDynamicSharedMemorySize,
                         SMEM_TOTAL);

    __half *xh, *sh, *wth, *gA, *gB, *gC;
    cudaGetSymbolAddress((void**)&xh,  g_Xh);
    cudaGetSymbolAddress((void**)&sh,  g_Sh);
    cudaGetSymbolAddress((void**)&wth, g_Wth);
    cudaGetSymbolAddress((void**)&gA,  g_Ah);
    cudaGetSymbolAddress((void**)&gB,  g_Bh);
    cudaGetSymbolAddress((void**)&gC,  g_Ch);
    __half* wt1 = wth;
    __half* wt2 = wt1 + (size_t)512 * 768;
    __half* wt3 = wt2 + (size_t)512 * 1536;
    __half* wtp = wt3 + (size_t)512 * 2304;

    // input conversions: grid-stride, MLP=4 (148 SMs x 8 blocks)
    cvt_inputs<<<1184, 256>>>(words, sentE);

    // weight transposes (one launch): kb blocks 24 | 48 | 72 | 24
    {
        TParams tp;
        tp.seg[0] = { W1, wt1, 768,  0 };
        tp.seg[1] = { W2, wt2, 1536, 24 };
        tp.seg[2] = { W3, wt3, 2304, 72 };
        tp.seg[3] = { Wp, wtp, 768,  144 };
        transpose_all<<<dim3(168, 16), dim3(32, 8)>>>(tp);
    }

    const int SSTRIDE = 20 * EMB;   // 15360

    // Merged GEMM: segments ordered longest-K first (conv3, conv2, conv1, sent)
    Params p;
    // conv3: M=73728 -> 576 mb x 2 = 1152 blocks
    p.seg[0] = { xh, wt3, b3, gC,       2304, 18, SSTRIDE, 1, 1, 0 };
    // conv2: M=77824 -> 608 x 2 = 1216
    p.seg[1] = { xh, wt2, b2, gB,       1536, 19, SSTRIDE, 1, 1, 1152 };
    // conv1: M=81920 -> 640 x 2 = 1280
    p.seg[2] = { xh, wt1, b1, gA,        768, 20, SSTRIDE, 1, 1, 2368 };
    // sent:  M=4096  -> 32 x 2 = 64 (f32 external output)
    p.seg[3] = { sh, wtp, bp, sent_out,  768,  1, EMB,     0, 0, 3648 };

    gemm_f16<<<3712, 512, SMEM_TOTAL>>>(p);

    epilogue_kernel<<<BS / 2, 512>>>(words_out, word_vec);
}

// round 16
// speedup vs baseline: 1.0830x; 1.0073x over previous
#include <cuda_runtime.h>
#include <cuda_fp16.h>
#include <cstdint>

// ---------------------------------------------------------------------------
// BERTHeading via warp-level mma.sync fp16 GEMMs (f32 accumulate).
// GEMM: round-10/13 proven config — merged 4-segment launch, 512 threads/CTA
// (16 warps, 64x32 warp tile), BM=128 x BN=256, K-chunk 32, 4-stage cp.async
// pipeline (race-free: wait_group 2 -> barrier -> prefetch(c+3) -> compute).
// fp16 scratch conv outputs. Single prep kernel (input cvt + weight
// transposes). Epilogue: 1 sample per 256-thread block (4 CTAs/SM).
// ---------------------------------------------------------------------------

#define BS      4096
#define EMB     768
#define FEAT    512

#define BM      128
#define BN      256
#define BKF     32                  // K elements per chunk
#define KPH     40                  // halves stride (80 B, ldmatrix conflict-free)
#define A_STG_B (BM * KPH * 2)      // 10240 B
#define B_STG_B (BN * KPH * 2)      // 20480 B
#define STG_B   (A_STG_B + B_STG_B) // 30720 B
#define STAGES  4
#define SMEM_TOTAL (STAGES * STG_B) // 122880 B

__device__ __half g_Ah[BS * 20 * FEAT];
__device__ __half g_Bh[BS * 19 * FEAT];
__device__ __half g_Ch[BS * 18 * FEAT];
__device__ __half g_Xh[BS * 20 * EMB];     // fp16 words_emb
__device__ __half g_Sh[BS * EMB];          // fp16 sent_emb
// transposed fp16 weights, [512, K] row-major: W1 | W2 | W3 | Wp
__device__ __half g_Wth[512 * (768 + 1536 + 2304 + 768)];

struct Seg {
    const __half* X;
    const __half* Wt;
    const float*  bias;
    void*         Y;
    int K, T, srcStride, doRelu, outHalf, blkStart;
};
struct Params { Seg seg[4]; };

struct TSeg { const float* W; __half* Wt; int K; int kbStart; };
struct PrepParams {
    TSeg seg[4];
    const float* words;
    const float* sent;
};

#define CP_ASYNC16(saddr, gptr) \
    asm volatile("cp.async.cg.shared.global [%0], [%1], 16;" :: "r"(saddr), "l"(gptr))
#define CP_COMMIT() asm volatile("cp.async.commit_group;" ::: "memory")
#define CP_WAIT2()  asm volatile("cp.async.wait_group 2;" ::: "memory")

// transpose blocks (168 kb x 16 nb) ride in front of cvt blocks
#define TR_BLOCKS   (168 * 16)      // 2688
#define CVT_BLOCKS  1184            // 148 SMs x 8, MLP-4 grid-stride
#define PREP_BLOCKS (TR_BLOCKS + CVT_BLOCKS)

__device__ __forceinline__ uint32_t smem_u32(const void* p) {
    uint32_t a;
    asm("{ .reg .u64 t; cvta.to.shared.u64 t, %1; cvt.u32.u64 %0, t; }"
        : "=r"(a) : "l"(p));
    return a;
}

__device__ __forceinline__ void mma_f16(float* d, const uint32_t* a,
                                        const uint32_t* b) {
    asm volatile(
        "mma.sync.aligned.m16n8k16.row.col.f32.f16.f16.f32 "
        "{%0,%1,%2,%3}, {%4,%5,%6,%7}, {%8,%9}, {%0,%1,%2,%3};"
        : "+f"(d[0]), "+f"(d[1]), "+f"(d[2]), "+f"(d[3])
        : "r"(a[0]), "r"(a[1]), "r"(a[2]), "r"(a[3]), "r"(b[0]), "r"(b[1]));
}

__device__ __forceinline__ void ldsm_x4(uint32_t* r, uint32_t addr) {
    asm volatile(
        "ldmatrix.sync.aligned.m8n8.x4.shared.b16 {%0,%1,%2,%3}, [%4];"
        : "=r"(r[0]), "=r"(r[1]), "=r"(r[2]), "=r"(r[3]) : "r"(addr));
}

// ---------------------------------------------------------------------------
// Prep kernel: weight transposes (blocks [0, TR_BLOCKS)) + f32->f16 input
// conversion (blocks [TR_BLOCKS, PREP_BLOCKS), grid-stride, MLP=4).
// ---------------------------------------------------------------------------
__device__ __forceinline__ void cvt_span(const float* __restrict__ src,
                                         __half2* __restrict__ dst,
                                         int n4, int i0, int gs)
{
    int i = i0;
    for (; i + 3 * gs < n4; i += 4 * gs) {
        float4 v0 = ((const float4*)src)[i];
        float4 v1 = ((const float4*)src)[i + gs];
        float4 v2 = ((const float4*)src)[i + 2 * gs];
        float4 v3 = ((const float4*)src)[i + 3 * gs];
        dst[2 * (size_t)i]                 = __floats2half2_rn(v0.x, v0.y);
        dst[2 * (size_t)i + 1]             = __floats2half2_rn(v0.z, v0.w);
        dst[2 * (size_t)(i + gs)]          = __floats2half2_rn(v1.x, v1.y);
        dst[2 * (size_t)(i + gs) + 1]      = __floats2half2_rn(v1.z, v1.w);
        dst[2 * (size_t)(i + 2 * gs)]      = __floats2half2_rn(v2.x, v2.y);
        dst[2 * (size_t)(i + 2 * gs) + 1]  = __floats2half2_rn(v2.z, v2.w);
        dst[2 * (size_t)(i + 3 * gs)]      = __floats2half2_rn(v3.x, v3.y);
        dst[2 * (size_t)(i + 3 * gs) + 1]  = __floats2half2_rn(v3.z, v3.w);
    }
    for (; i < n4; i += gs) {
        float4 v = ((const float4*)src)[i];
        dst[2 * (size_t)i]     = __floats2half2_rn(v.x, v.y);
        dst[2 * (size_t)i + 1] = __floats2half2_rn(v.z, v.w);
    }
}

__global__ void __launch_bounds__(256)
prep_kernel(PrepParams p)
{
    const int bid = blockIdx.x;
    const int tid = threadIdx.x;

    if (bid < TR_BLOCKS) {
        // ---- weight transpose: W [K,512] -> Wt [512,K] fp16 ----
        const int kbb = bid >> 4;          // 0..167 (32-K block)
        const int nbb = bid & 15;          // 0..15  (32-N block)
        const int sid = (kbb >= p.seg[1].kbStart) + (kbb >= p.seg[2].kbStart)
                      + (kbb >= p.seg[3].kbStart);
        const TSeg sg = p.seg[sid];

        __shared__ float t[32][33];
        const int kb = (kbb - sg.kbStart) * 32, nb = nbb * 32;
        const int x = tid & 31, y = tid >> 5;   // 32 x 8
        #pragma unroll
        for (int i = 0; i < 32; i += 8)
            t[y + i][x] = sg.W[(size_t)(kb + y + i) * FEAT + nb + x];
        __syncthreads();
        #pragma unroll
        for (int i = 0; i < 32; i += 8)
            sg.Wt[(size_t)(nb + y + i) * sg.K + kb + x] =
                __float2half_rn(t[x][y + i]);
    } else {
        // ---- input conversion ----
        const int gs = CVT_BLOCKS * 256;
        const int i0 = (bid - TR_BLOCKS) * 256 + tid;
        cvt_span(p.words, (__half2*)g_Xh, BS * 20 * EMB / 4, i0, gs);
        cvt_span(p.sent,  (__half2*)g_Sh, BS * EMB / 4,      i0, gs);
    }
}

// ---------------------------------------------------------------------------
// Merged fp16 mma.sync GEMM (4 segments in one grid).
//   Y[m, nb..nb+255] = act( A(m,:) @ Wt[nb..nb+255,:]^T + bias )
//   A(m,:) = X + (m/T)*srcStride + (m%T)*768, contiguous K halves.
// 512 threads: 16 warps, 2 m-warps x 8 n-warps, 64x32 warp tile.
// ---------------------------------------------------------------------------
__global__ void __launch_bounds__(512, 1)
gemm_f16(Params p)
{
    extern __shared__ char smem[];
    const int bid = blockIdx.x;
    const int sid = (bid >= p.seg[1].blkStart) + (bid >= p.seg[2].blkStart)
                  + (bid >= p.seg[3].blkStart);
    const Seg sg = p.seg[sid];

    const int idx = bid - sg.blkStart;
    const int mb  = idx >> 1;          // m-tile
    const int nb  = (idx & 1) * BN;    // n offset (FEAT/BN == 2)

    const int tid  = threadIdx.x;
    const int lane = tid & 31;
    const int wid  = tid >> 5;         // 0..15
    const int wm   = wid & 1;          // 2 m-warps (64 rows each)
    const int wn   = wid >> 1;         // 8 n-warps (32 cols each)
    const int r    = lane >> 2;        // 0..7
    const int cq   = lane & 3;         // 0..3

    const uint32_t sbase = smem_u32(smem);

    // ---- loader addresses (512 threads) ----
    // A: 128 rows x 64 B; thread t -> row t/4, 16B chunk t%4 (1 cp.async)
    const int am = mb * BM + (tid >> 2);
    const __half* aRow = sg.X + (size_t)(am / sg.T) * sg.srcStride
                              + (size_t)(am % sg.T) * EMB + (tid & 3) * 8;
    const uint32_t aDst = sbase + ((tid >> 2) * KPH + (tid & 3) * 8) * 2;
    // B: 256 rows x 64 B; thread t -> row t/2, 32 B half (2 cp.async of 16 B)
    const __half* bRow = sg.Wt + (size_t)(nb + (tid >> 1)) * sg.K + (tid & 1) * 16;
    const uint32_t bDst = sbase + A_STG_B
                        + ((tid >> 1) * KPH + (tid & 1) * 16) * 2;

    const int Kc = sg.K / BKF;

    auto load_chunk = [&](int chunk) {
        const uint32_t so = (uint32_t)((chunk & (STAGES - 1)) * STG_B);
        const int kc = chunk * BKF;
        CP_ASYNC16(aDst + so, aRow + kc);
        CP_ASYNC16(bDst + so,      bRow + kc);       // bytes [x*32, x*32+16)
        CP_ASYNC16(bDst + so + 16, bRow + kc + 8);   // bytes [x*32+16, x*32+32)
    };

    float acc[4][4][4];
    #pragma unroll
    for (int mi = 0; mi < 4; mi++)
        #pragma unroll
        for (int nj = 0; nj < 4; nj++)
            #pragma unroll
            for (int q = 0; q < 4; q++) acc[mi][nj][q] = 0.0f;

    load_chunk(0); CP_COMMIT();
    load_chunk(1); CP_COMMIT();
    load_chunk(2); CP_COMMIT();

    // ldmatrix.x4 lane mapping: matrices {rows0-7@k0, rows8-15@k0,
    // rows0-7@k8, rows8-15@k8} of a 16x16-half block.
    const int rowOff = ((lane >> 3) & 1) * 8 + (lane & 7);
    const int khOff  = (lane >> 4) * 8;
    const uint32_t aFragBase =
        sbase + ((wm * 64 + rowOff) * KPH + khOff) * 2;
    const uint32_t bFragBase =
        sbase + A_STG_B + ((wn * 32 + rowOff) * KPH + khOff) * 2;

    for (int c = 0; c < Kc; c++) {
        // Race-free protocol:
        CP_WAIT2();                      // own cp.asyncs for chunk c landed
        __syncthreads();                 // => everyone's chunk c landed, and
                                         //    all warps finished reading c-1
        if (c + 3 < Kc) load_chunk(c + 3);   // overwrites stage of c-1: safe
        CP_COMMIT();                     // (possibly empty group; keeps count)

        const uint32_t so = (uint32_t)((c & (STAGES - 1)) * STG_B);

        #pragma unroll
        for (int ks = 0; ks < 2; ks++) {       // two k16 steps per 32-chunk
            uint32_t af[4][4];
            #pragma unroll
            for (int mi = 0; mi < 4; mi++)
                ldsm_x4(af[mi], aFragBase + so + (mi * 16 * KPH + ks * 16) * 2);
            uint32_t bf[2][4];   // [njp]: {nEven.b0, nOdd.b0, nEven.b1, nOdd.b1}
            #pragma unroll
            for (int njp = 0; njp < 2; njp++)
                ldsm_x4(bf[njp], bFragBase + so + (njp * 16 * KPH + ks * 16) * 2);

            #pragma unroll
            for (int mi = 0; mi < 4; mi++)
                #pragma unroll
                for (int njp = 0; njp < 2; njp++) {
                    uint32_t b0[2] = { bf[njp][0], bf[njp][2] };
                    uint32_t b1[2] = { bf[njp][1], bf[njp][3] };
                    mma_f16(acc[mi][2 * njp + 0], af[mi], b0);
                    mma_f16(acc[mi][2 * njp + 1], af[mi], b1);
                }
        }
    }

    // ---- epilogue: bias (+relu), write Y (fp16 scratch or f32 external) ----
    const int mBase = mb * BM + wm * 64 + r;
    const int nBase = nb + wn * 32 + cq * 2;
    float bb[4][2];
    #pragma unroll
    for (int nj = 0; nj < 4; nj++) {
        bb[nj][0] = __ldg(sg.bias + nBase + nj * 8);
        bb[nj][1] = __ldg(sg.bias + nBase + nj * 8 + 1);
    }
    #pragma unroll
    for (int mi = 0; mi < 4; mi++) {
        #pragma unroll
        for (int rr = 0; rr < 2; rr++) {
            const size_t rowOffY = (size_t)(mBase + mi * 16 + rr * 8) * FEAT;
            #pragma unroll
            for (int nj = 0; nj < 4; nj++) {
                float v0 = acc[mi][nj][rr * 2 + 0] + bb[nj][0];
                float v1 = acc[mi][nj][rr * 2 + 1] + bb[nj][1];
                if (sg.doRelu) { v0 = fmaxf(v0, 0.0f); v1 = fmaxf(v1, 0.0f); }
                if (sg.outHalf) {
                    __half2* yh = (__half2*)((__half*)sg.Y + rowOffY + nBase + nj * 8);
                    *yh = __floats2half2_rn(v0, v1);
                } else {
                    float* yf = (float*)sg.Y + rowOffY + nBase + nj * 8;
                    *(float2*)yf = make_float2(v0, v1);
                }
            }
        }
    }
}

// ---------------------------------------------------------------------------
// Epilogue: 1 sample per 256-thread block (44 KB smem -> 4 CTAs/SM for
// latency hiding). Thread u owns feature pair (2u, 2u+1), loading __half2.
// Per-token L2 norms via 8-warp reduction; normalized values staged in f32
// smem (stride 21), then words_out written fully coalesced.
// ---------------------------------------------------------------------------
__global__ void __launch_bounds__(256)
epilogue_kernel(float* __restrict__ words_out, float* __restrict__ word_vec)
{
    const int u    = threadIdx.x;       // feature pair index 0..255
    const int lane = u & 31;
    const int w8   = u >> 5;            // warp 0..7
    const int s    = blockIdx.x;

    __shared__ float scode[512 * 21];   // 43008 B
    __shared__ float red[21][8];
    __shared__ float invn[21];

    const __half2* Ab = (const __half2*)(g_Ah + (size_t)s * 20 * FEAT) + u;
    const __half2* Bb = (const __half2*)(g_Bh + (size_t)s * 19 * FEAT) + u;
    const __half2* Cb = (const __half2*)(g_Ch + (size_t)s * 18 * FEAT) + u;

    float code0[20], code1[20];
    float ma0 = 0.0f, mb0 = 0.0f, mc0 = 0.0f;
    float ma1 = 0.0f, mb1 = 0.0f, mc1 = 0.0f;
    const int H = FEAT / 2;   // 256 half2 per row

    #pragma unroll
    for (int t = 0; t < 20; t++) {
        float2 av = __half22float2(Ab[t * H]);
        float2 bv = (t < 19) ? __half22float2(Bb[t * H]) : make_float2(0.f, 0.f);
        float2 cv = (t < 18) ? __half22float2(Cb[t * H]) : make_float2(0.f, 0.f);
        ma0 = fmaxf(ma0, av.x);  ma1 = fmaxf(ma1, av.y);
        mb0 = fmaxf(mb0, bv.x);  mb1 = fmaxf(mb1, bv.y);
        mc0 = fmaxf(mc0, cv.x);  mc1 = fmaxf(mc1, cv.y);
        float cd0 = fmaxf(av.x, fmaxf(bv.x, cv.x));
        float cd1 = fmaxf(av.y, fmaxf(bv.y, cv.y));
        code0[t] = cd0;
        code1[t] = cd1;
        float ss = cd0 * cd0 + cd1 * cd1;
        #pragma unroll
        for (int o = 16; o > 0; o >>= 1) ss += __shfl_xor_sync(0xffffffffu, ss, o);
        if (lane == 0) red[t][w8] = ss;
    }

    float pooled0 = (ma0 + mb0 + mc0) * (1.0f / 3.0f);
    float pooled1 = (ma1 + mb1 + mc1) * (1.0f / 3.0f);
    {
        float ps = pooled0 * pooled0 + pooled1 * pooled1;
        #pragma unroll
        for (int o = 16; o > 0; o >>= 1) ps += __shfl_xor_sync(0xffffffffu, ps, o);
        if (lane == 0) red[20][w8] = ps;
    }
    __syncthreads();

    if (u < 21) {
        float ssum = 0.0f;
        #pragma unroll
        for (int i = 0; i < 8; i++) ssum += red[u][i];
        invn[u] = 1.0f / fmaxf(sqrtf(ssum), 1e-12f);
    }
    __syncthreads();

    // stage normalized values: feature c at scode[c*21 + t]
    {
        float* s0 = &scode[(2 * u) * 21];
        float* s1 = s0 + 21;
        #pragma unroll
        for (int t = 0; t < 20; t++) {
            const float iv = invn[t];
            s0[t] = code0[t] * iv;
            s1[t] = code1[t] * iv;
        }
    }
    __syncthreads();

    // coalesced words_out write: 512*20 floats = 2560 float4 / 256 thr = 10
    float* op = words_out + (size_t)s * FEAT * 20;
    #pragma unroll
    for (int q = 0; q < 10; q++) {
        const int g = (q * 256 + u) * 4;
        float4 v;
        #pragma unroll
        for (int e = 0; e < 4; e++) {
            const int gi = g + e;
            const int cc = gi / 20;
            const int tt = gi - cc * 20;
            ((float*)&v)[e] = scode[cc * 21 + tt];
        }
        *(float4*)(op + g) = v;
    }

    const float ivp = invn[20];
    *(float2*)(word_vec + (size_t)s * FEAT + 2 * u) =
        make_float2(pooled0 * ivp, pooled1 * ivp);
}

// ---------------------------------------------------------------------------
extern "C" void kernel_launch(void* const* d_in, const int* in_sizes, int n_in,
                              void* d_out, int out_size)
{
    const float* words = (const float*)d_in[0];
    const float* sentE = (const float*)d_in[1];
    const float* W1 = (const float*)d_in[2];
    const float* b1 = (const float*)d_in[3];
    const float* W2 = (const float*)d_in[4];
    const float* b2 = (const float*)d_in[5];
    const float* W3 = (const float*)d_in[6];
    const float* b3 = (const float*)d_in[7];
    const float* Wp = (const float*)d_in[8];
    const float* bp = (const float*)d_in[9];

    float* out       = (float*)d_out;
    float* words_out = out;
    float* word_vec  = out + (size_t)BS * FEAT * 20;
    float* sent_out  = word_vec + (size_t)BS * FEAT;

    cudaFuncSetAttribute(gemm_f16, cudaFuncAttributeMaxDynamicSharedMemorySize,
                         SMEM_TOTAL);

    __half *xh, *sh, *wth, *gA, *gB, *gC;
    cudaGetSymbolAddress((void**)&xh,  g_Xh);
    cudaGetSymbolAddress((void**)&sh,  g_Sh);
    cudaGetSymbolAddress((void**)&wth, g_Wth);
    cudaGetSymbolAddress((void**)&gA,  g_Ah);
    cudaGetSymbolAddress((void**)&gB,  g_Bh);
    cudaGetSymbolAddress((void**)&gC,  g_Ch);
    __half* wt1 = wth;
    __half* wt2 = wt1 + (size_t)512 * 768;
    __half* wt3 = wt2 + (size_t)512 * 1536;
    __half* wtp = wt3 + (size_t)512 * 2304;

    // prep: weight transposes + input conversion in one launch
    {
        PrepParams pp;
        pp.seg[0] = { W1, wt1, 768,  0 };
        pp.seg[1] = { W2, wt2, 1536, 24 };
        pp.seg[2] = { W3, wt3, 2304, 72 };
        pp.seg[3] = { Wp, wtp, 768,  144 };
        pp.words = words;
        pp.sent  = sentE;
        prep_kernel<<<PREP_BLOCKS, 256>>>(pp);
    }

    const int SSTRIDE = 20 * EMB;   // 15360

    // Merged GEMM: segments ordered longest-K first (conv3, conv2, conv1, sent)
    Params p;
    // conv3: M=73728 -> 576 mb x 2 = 1152 blocks
    p.seg[0] = { xh, wt3, b3, gC,       2304, 18, SSTRIDE, 1, 1, 0 };
    // conv2: M=77824 -> 608 x 2 = 1216
    p.seg[1] = { xh, wt2, b2, gB,       1536, 19, SSTRIDE, 1, 1, 1152 };
    // conv1: M=81920 -> 640 x 2 = 1280
    p.seg[2] = { xh, wt1, b1, gA,        768, 20, SSTRIDE, 1, 1, 2368 };
    // sent:  M=4096  -> 32 x 2 = 64 (f32 external output)
    p.seg[3] = { sh, wtp, bp, sent_out,  768,  1, EMB,     0, 0, 3648 };

    gemm_f16<<<3712, 512, SMEM_TOTAL>>>(p);

    epilogue_kernel<<<BS, 256>>>(words_out, word_vec);
}

// round 17
// speedup vs baseline: 1.0866x; 1.0033x over previous
#include <cuda_runtime.h>
#include <cuda_fp16.h>
#include <cstdint>

// ---------------------------------------------------------------------------
// BERTHeading via warp-level mma.sync fp16 GEMMs (f32 accumulate).
// GEMM: round-10/13 proven config — merged 4-segment launch, 512 threads/CTA
// (16 warps, 64x32 warp tile), BM=128 x BN=256, K-chunk 32, 4-stage cp.async
// pipeline (race-free: wait_group 2 -> barrier -> prefetch(c+3) -> compute).
// fp16 scratch conv outputs. Single prep kernel (weight transposes + input
// cvt with 16B stores, MLP=8). Epilogue: 1 sample/256-thr block (4 CTAs/SM).
// ---------------------------------------------------------------------------

#define BS      4096
#define EMB     768
#define FEAT    512

#define BM      128
#define BN      256
#define BKF     32                  // K elements per chunk
#define KPH     40                  // halves stride (80 B, ldmatrix conflict-free)
#define A_STG_B (BM * KPH * 2)      // 10240 B
#define B_STG_B (BN * KPH * 2)      // 20480 B
#define STG_B   (A_STG_B + B_STG_B) // 30720 B
#define STAGES  4
#define SMEM_TOTAL (STAGES * STG_B) // 122880 B

__device__ __half g_Ah[BS * 20 * FEAT];
__device__ __half g_Bh[BS * 19 * FEAT];
__device__ __half g_Ch[BS * 18 * FEAT];
__device__ __half g_Xh[BS * 20 * EMB];     // fp16 words_emb
__device__ __half g_Sh[BS * EMB];          // fp16 sent_emb
// transposed fp16 weights, [512, K] row-major: W1 | W2 | W3 | Wp
__device__ __half g_Wth[512 * (768 + 1536 + 2304 + 768)];

struct Seg {
    const __half* X;
    const __half* Wt;
    const float*  bias;
    void*         Y;
    int K, T, srcStride, doRelu, outHalf, blkStart;
};
struct Params { Seg seg[4]; };

struct TSeg { const float* W; __half* Wt; int K; int kbStart; };
struct PrepParams {
    TSeg seg[4];
    const float* words;
    const float* sent;
};

#define CP_ASYNC16(saddr, gptr) \
    asm volatile("cp.async.cg.shared.global [%0], [%1], 16;" :: "r"(saddr), "l"(gptr))
#define CP_COMMIT() asm volatile("cp.async.commit_group;" ::: "memory")
#define CP_WAIT2()  asm volatile("cp.async.wait_group 2;" ::: "memory")

// transpose blocks (168 kb x 16 nb) ride in front of cvt blocks
#define TR_BLOCKS   (168 * 16)      // 2688
#define CVT_BLOCKS  1184            // 148 SMs x 8, MLP-8 grid-stride
#define PREP_BLOCKS (TR_BLOCKS + CVT_BLOCKS)

__device__ __forceinline__ uint32_t smem_u32(const void* p) {
    uint32_t a;
    asm("{ .reg .u64 t; cvta.to.shared.u64 t, %1; cvt.u32.u64 %0, t; }"
        : "=r"(a) : "l"(p));
    return a;
}

__device__ __forceinline__ void mma_f16(float* d, const uint32_t* a,
                                        const uint32_t* b) {
    asm volatile(
        "mma.sync.aligned.m16n8k16.row.col.f32.f16.f16.f32 "
        "{%0,%1,%2,%3}, {%4,%5,%6,%7}, {%8,%9}, {%0,%1,%2,%3};"
        : "+f"(d[0]), "+f"(d[1]), "+f"(d[2]), "+f"(d[3])
        : "r"(a[0]), "r"(a[1]), "r"(a[2]), "r"(a[3]), "r"(b[0]), "r"(b[1]));
}

__device__ __forceinline__ void ldsm_x4(uint32_t* r, uint32_t addr) {
    asm volatile(
        "ldmatrix.sync.aligned.m8n8.x4.shared.b16 {%0,%1,%2,%3}, [%4];"
        : "=r"(r[0]), "=r"(r[1]), "=r"(r[2]), "=r"(r[3]) : "r"(addr));
}

// ---------------------------------------------------------------------------
// Prep kernel: weight transposes (blocks [0, TR_BLOCKS)) + f32->f16 input
// conversion (blocks [TR_BLOCKS, PREP_BLOCKS)).
// cvt: group i = 8 floats (two float4 loads) -> one 16 B store of 4 half2.
// 4-way unrolled grid-stride -> 8 LDG.128 in flight, 4 STG.128 per iter.
// ---------------------------------------------------------------------------
__device__ __forceinline__ void cvt_group(const float4* __restrict__ s4,
                                          float4* __restrict__ d4, size_t i)
{
    float4 a = s4[2 * i];
    float4 b = s4[2 * i + 1];
    __half2 h[4];
    h[0] = __floats2half2_rn(a.x, a.y);
    h[1] = __floats2half2_rn(a.z, a.w);
    h[2] = __floats2half2_rn(b.x, b.y);
    h[3] = __floats2half2_rn(b.z, b.w);
    d4[i] = *(float4*)h;
}

__device__ __forceinline__ void cvt_span(const float* __restrict__ src,
                                         __half* __restrict__ dst,
                                         int n8, int i0, int gs)
{
    const float4* s4 = (const float4*)src;
    float4* d4 = (float4*)dst;
    int i = i0;
    for (; i + 3 * gs < n8; i += 4 * gs) {
        cvt_group(s4, d4, i);
        cvt_group(s4, d4, i + gs);
        cvt_group(s4, d4, i + 2 * gs);
        cvt_group(s4, d4, i + 3 * gs);
    }
    for (; i < n8; i += gs)
        cvt_group(s4, d4, i);
}

__global__ void __launch_bounds__(256)
prep_kernel(PrepParams p)
{
    const int bid = blockIdx.x;
    const int tid = threadIdx.x;

    if (bid < TR_BLOCKS) {
        // ---- weight transpose: W [K,512] -> Wt [512,K] fp16 ----
        const int kbb = bid >> 4;          // 0..167 (32-K block)
        const int nbb = bid & 15;          // 0..15  (32-N block)
        const int sid = (kbb >= p.seg[1].kbStart) + (kbb >= p.seg[2].kbStart)
                      + (kbb >= p.seg[3].kbStart);
        const TSeg sg = p.seg[sid];

        __shared__ float t[32][33];
        const int kb = (kbb - sg.kbStart) * 32, nb = nbb * 32;
        const int x = tid & 31, y = tid >> 5;   // 32 x 8
        #pragma unroll
        for (int i = 0; i < 32; i += 8)
            t[y + i][x] = sg.W[(size_t)(kb + y + i) * FEAT + nb + x];
        __syncthreads();
        #pragma unroll
        for (int i = 0; i < 32; i += 8)
            sg.Wt[(size_t)(nb + y + i) * sg.K + kb + x] =
                __float2half_rn(t[x][y + i]);
    } else {
        // ---- input conversion (8-float groups) ----
        const int gs = CVT_BLOCKS * 256;
        const int i0 = (bid - TR_BLOCKS) * 256 + tid;
        cvt_span(p.words, g_Xh, BS * 20 * EMB / 8, i0, gs);
        cvt_span(p.sent,  g_Sh, BS * EMB / 8,      i0, gs);
    }
}

// ---------------------------------------------------------------------------
// Merged fp16 mma.sync GEMM (4 segments in one grid).
//   Y[m, nb..nb+255] = act( A(m,:) @ Wt[nb..nb+255,:]^T + bias )
//   A(m,:) = X + (m/T)*srcStride + (m%T)*768, contiguous K halves.
// 512 threads: 16 warps, 2 m-warps x 8 n-warps, 64x32 warp tile.
// ---------------------------------------------------------------------------
__global__ void __launch_bounds__(512, 1)
gemm_f16(Params p)
{
    extern __shared__ char smem[];
    const int bid = blockIdx.x;
    const int sid = (bid >= p.seg[1].blkStart) + (bid >= p.seg[2].blkStart)
                  + (bid >= p.seg[3].blkStart);
    const Seg sg = p.seg[sid];

    const int idx = bid - sg.blkStart;
    const int mb  = idx >> 1;          // m-tile
    const int nb  = (idx & 1) * BN;    // n offset (FEAT/BN == 2)

    const int tid  = threadIdx.x;
    const int lane = tid & 31;
    const int wid  = tid >> 5;         // 0..15
    const int wm   = wid & 1;          // 2 m-warps (64 rows each)
    const int wn   = wid >> 1;         // 8 n-warps (32 cols each)
    const int r    = lane >> 2;        // 0..7
    const int cq   = lane & 3;         // 0..3

    const uint32_t sbase = smem_u32(smem);

    // ---- loader addresses (512 threads) ----
    // A: 128 rows x 64 B; thread t -> row t/4, 16B chunk t%4 (1 cp.async)
    const int am = mb * BM + (tid >> 2);
    const __half* aRow = sg.X + (size_t)(am / sg.T) * sg.srcStride
                              + (size_t)(am % sg.T) * EMB + (tid & 3) * 8;
    const uint32_t aDst = sbase + ((tid >> 2) * KPH + (tid & 3) * 8) * 2;
    // B: 256 rows x 64 B; thread t -> row t/2, 32 B half (2 cp.async of 16 B)
    const __half* bRow = sg.Wt + (size_t)(nb + (tid >> 1)) * sg.K + (tid & 1) * 16;
    const uint32_t bDst = sbase + A_STG_B
                        + ((tid >> 1) * KPH + (tid & 1) * 16) * 2;

    const int Kc = sg.K / BKF;

    auto load_chunk = [&](int chunk) {
        const uint32_t so = (uint32_t)((chunk & (STAGES - 1)) * STG_B);
        const int kc = chunk * BKF;
        CP_ASYNC16(aDst + so, aRow + kc);
        CP_ASYNC16(bDst + so,      bRow + kc);       // bytes [x*32, x*32+16)
        CP_ASYNC16(bDst + so + 16, bRow + kc + 8);   // bytes [x*32+16, x*32+32)
    };

    float acc[4][4][4];
    #pragma unroll
    for (int mi = 0; mi < 4; mi++)
        #pragma unroll
        for (int nj = 0; nj < 4; nj++)
            #pragma unroll
            for (int q = 0; q < 4; q++) acc[mi][nj][q] = 0.0f;

    load_chunk(0); CP_COMMIT();
    load_chunk(1); CP_COMMIT();
    load_chunk(2); CP_COMMIT();

    // ldmatrix.x4 lane mapping: matrices {rows0-7@k0, rows8-15@k0,
    // rows0-7@k8, rows8-15@k8} of a 16x16-half block.
    const int rowOff = ((lane >> 3) & 1) * 8 + (lane & 7);
    const int khOff  = (lane >> 4) * 8;
    const uint32_t aFragBase =
        sbase + ((wm * 64 + rowOff) * KPH + khOff) * 2;
    const uint32_t bFragBase =
        sbase + A_STG_B + ((wn * 32 + rowOff) * KPH + khOff) * 2;

    for (int c = 0; c < Kc; c++) {
        // Race-free protocol:
        CP_WAIT2();                      // own cp.asyncs for chunk c landed
        __syncthreads();                 // => everyone's chunk c landed, and
                                         //    all warps finished reading c-1
        if (c + 3 < Kc) load_chunk(c + 3);   // overwrites stage of c-1: safe
        CP_COMMIT();                     // (possibly empty group; keeps count)

        const uint32_t so = (uint32_t)((c & (STAGES - 1)) * STG_B);

        #pragma unroll
        for (int ks = 0; ks < 2; ks++) {       // two k16 steps per 32-chunk
            uint32_t af[4][4];
            #pragma unroll
            for (int mi = 0; mi < 4; mi++)
                ldsm_x4(af[mi], aFragBase + so + (mi * 16 * KPH + ks * 16) * 2);
            uint32_t bf[2][4];   // [njp]: {nEven.b0, nOdd.b0, nEven.b1, nOdd.b1}
            #pragma unroll
            for (int njp = 0; njp < 2; njp++)
                ldsm_x4(bf[njp], bFragBase + so + (njp * 16 * KPH + ks * 16) * 2);

            #pragma unroll
            for (int mi = 0; mi < 4; mi++)
                #pragma unroll
                for (int njp = 0; njp < 2; njp++) {
                    uint32_t b0[2] = { bf[njp][0], bf[njp][2] };
                    uint32_t b1[2] = { bf[njp][1], bf[njp][3] };
                    mma_f16(acc[mi][2 * njp + 0], af[mi], b0);
                    mma_f16(acc[mi][2 * njp + 1], af[mi], b1);
                }
        }
    }

    // ---- epilogue: bias (+relu), write Y (fp16 scratch or f32 external) ----
    const int mBase = mb * BM + wm * 64 + r;
    const int nBase = nb + wn * 32 + cq * 2;
    float bb[4][2];
    #pragma unroll
    for (int nj = 0; nj < 4; nj++) {
        bb[nj][0] = __ldg(sg.bias + nBase + nj * 8);
        bb[nj][1] = __ldg(sg.bias + nBase + nj * 8 + 1);
    }
    #pragma unroll
    for (int mi = 0; mi < 4; mi++) {
        #pragma unroll
        for (int rr = 0; rr < 2; rr++) {
            const size_t rowOffY = (size_t)(mBase + mi * 16 + rr * 8) * FEAT;
            #pragma unroll
            for (int nj = 0; nj < 4; nj++) {
                float v0 = acc[mi][nj][rr * 2 + 0] + bb[nj][0];
                float v1 = acc[mi][nj][rr * 2 + 1] + bb[nj][1];
                if (sg.doRelu) { v0 = fmaxf(v0, 0.0f); v1 = fmaxf(v1, 0.0f); }
                if (sg.outHalf) {
                    __half2* yh = (__half2*)((__half*)sg.Y + rowOffY + nBase + nj * 8);
                    *yh = __floats2half2_rn(v0, v1);
                } else {
                    float* yf = (float*)sg.Y + rowOffY + nBase + nj * 8;
                    *(float2*)yf = make_float2(v0, v1);
                }
            }
        }
    }
}

// ---------------------------------------------------------------------------
// Epilogue: 1 sample per 256-thread block (44 KB smem -> 4 CTAs/SM for
// latency hiding). Thread u owns feature pair (2u, 2u+1), loading __half2.
// Per-token L2 norms via 8-warp reduction; normalized values staged in f32
// smem (stride 21), then words_out written fully coalesced.
// ---------------------------------------------------------------------------
__global__ void __launch_bounds__(256)
epilogue_kernel(float* __restrict__ words_out, float* __restrict__ word_vec)
{
    const int u    = threadIdx.x;       // feature pair index 0..255
    const int lane = u & 31;
    const int w8   = u >> 5;            // warp 0..7
    const int s    = blockIdx.x;

    __shared__ float scode[512 * 21];   // 43008 B
    __shared__ float red[21][8];
    __shared__ float invn[21];

    const __half2* Ab = (const __half2*)(g_Ah + (size_t)s * 20 * FEAT) + u;
    const __half2* Bb = (const __half2*)(g_Bh + (size_t)s * 19 * FEAT) + u;
    const __half2* Cb = (const __half2*)(g_Ch + (size_t)s * 18 * FEAT) + u;

    float code0[20], code1[20];
    float ma0 = 0.0f, mb0 = 0.0f, mc0 = 0.0f;
    float ma1 = 0.0f, mb1 = 0.0f, mc1 = 0.0f;
    const int H = FEAT / 2;   // 256 half2 per row

    #pragma unroll
    for (int t = 0; t < 20; t++) {
        float2 av = __half22float2(Ab[t * H]);
        float2 bv = (t < 19) ? __half22float2(Bb[t * H]) : make_float2(0.f, 0.f);
        float2 cv = (t < 18) ? __half22float2(Cb[t * H]) : make_float2(0.f, 0.f);
        ma0 = fmaxf(ma0, av.x);  ma1 = fmaxf(ma1, av.y);
        mb0 = fmaxf(mb0, bv.x);  mb1 = fmaxf(mb1, bv.y);
        mc0 = fmaxf(mc0, cv.x);  mc1 = fmaxf(mc1, cv.y);
        float cd0 = fmaxf(av.x, fmaxf(bv.x, cv.x));
        float cd1 = fmaxf(av.y, fmaxf(bv.y, cv.y));
        code0[t] = cd0;
        code1[t] = cd1;
        float ss = cd0 * cd0 + cd1 * cd1;
        #pragma unroll
        for (int o = 16; o > 0; o >>= 1) ss += __shfl_xor_sync(0xffffffffu, ss, o);
        if (lane == 0) red[t][w8] = ss;
    }

    float pooled0 = (ma0 + mb0 + mc0) * (1.0f / 3.0f);
    float pooled1 = (ma1 + mb1 + mc1) * (1.0f / 3.0f);
    {
        float ps = pooled0 * pooled0 + pooled1 * pooled1;
        #pragma unroll
        for (int o = 16; o > 0; o >>= 1) ps += __shfl_xor_sync(0xffffffffu, ps, o);
        if (lane == 0) red[20][w8] = ps;
    }
    __syncthreads();

    if (u < 21) {
        float ssum = 0.0f;
        #pragma unroll
        for (int i = 0; i < 8; i++) ssum += red[u][i];
        invn[u] = 1.0f / fmaxf(sqrtf(ssum), 1e-12f);
    }
    __syncthreads();

    // stage normalized values: feature c at scode[c*21 + t]
    {
        float* s0 = &scode[(2 * u) * 21];
        float* s1 = s0 + 21;
        #pragma unroll
        for (int t = 0; t < 20; t++) {
            const float iv = invn[t];
            s0[t] = code0[t] * iv;
            s1[t] = code1[t] * iv;
        }
    }
    __syncthreads();

    // coalesced words_out write: 512*20 floats = 2560 float4 / 256 thr = 10
    float* op = words_out + (size_t)s * FEAT * 20;
    #pragma unroll
    for (int q = 0; q < 10; q++) {
        const int g = (q * 256 + u) * 4;
        float4 v;
        #pragma unroll
        for (int e = 0; e < 4; e++) {
            const int gi = g + e;
            const int cc = gi / 20;
            const int tt = gi - cc * 20;
            ((float*)&v)[e] = scode[cc * 21 + tt];
        }
        *(float4*)(op + g) = v;
    }

    const float ivp = invn[20];
    *(float2*)(word_vec + (size_t)s * FEAT + 2 * u) =
        make_float2(pooled0 * ivp, pooled1 * ivp);
}

// ---------------------------------------------------------------------------
extern "C" void kernel_launch(void* const* d_in, const int* in_sizes, int n_in,
                              void* d_out, int out_size)
{
    const float* words = (const float*)d_in[0];
    const float* sentE = (const float*)d_in[1];
    const float* W1 = (const float*)d_in[2];
    const float* b1 = (const float*)d_in[3];
    const float* W2 = (const float*)d_in[4];
    const float* b2 = (const float*)d_in[5];
    const float* W3 = (const float*)d_in[6];
    const float* b3 = (const float*)d_in[7];
    const float* Wp = (const float*)d_in[8];
    const float* bp = (const float*)d_in[9];

    float* out       = (float*)d_out;
    float* words_out = out;
    float* word_vec  = out + (size_t)BS * FEAT * 20;
    float* sent_out  = word_vec + (size_t)BS * FEAT;

    cudaFuncSetAttribute(gemm_f16, cudaFuncAttributeMaxDynamicSharedMemorySize,
                         SMEM_TOTAL);

    __half *xh, *sh, *wth, *gA, *gB, *gC;
    cudaGetSymbolAddress((void**)&xh,  g_Xh);
    cudaGetSymbolAddress((void**)&sh,  g_Sh);
    cudaGetSymbolAddress((void**)&wth, g_Wth);
    cudaGetSymbolAddress((void**)&gA,  g_Ah);
    cudaGetSymbolAddress((void**)&gB,  g_Bh);
    cudaGetSymbolAddress((void**)&gC,  g_Ch);
    __half* wt1 = wth;
    __half* wt2 = wt1 + (size_t)512 * 768;
    __half* wt3 = wt2 + (size_t)512 * 1536;
    __half* wtp = wt3 + (size_t)512 * 2304;

    // prep: weight transposes + input conversion in one launch
    {
        PrepParams pp;
        pp.seg[0] = { W1, wt1, 768,  0 };
        pp.seg[1] = { W2, wt2, 1536, 24 };
        pp.seg[2] = { W3, wt3, 2304, 72 };
        pp.seg[3] = { Wp, wtp, 768,  144 };
        pp.words = words;
        pp.sent  = sentE;
        prep_kernel<<<PREP_BLOCKS, 256>>>(pp);
    }

    const int SSTRIDE = 20 * EMB;   // 15360

    // Merged GEMM: segments ordered longest-K first (conv3, conv2, conv1, sent)
    Params p;
    // conv3: M=73728 -> 576 mb x 2 = 1152 blocks
    p.seg[0] = { xh, wt3, b3, gC,       2304, 18, SSTRIDE, 1, 1, 0 };
    // conv2: M=77824 -> 608 x 2 = 1216
    p.seg[1] = { xh, wt2, b2, gB,       1536, 19, SSTRIDE, 1, 1, 1152 };
    // conv1: M=81920 -> 640 x 2 = 1280
    p.seg[2] = { xh, wt1, b1, gA,        768, 20, SSTRIDE, 1, 1, 2368 };
    // sent:  M=4096  -> 32 x 2 = 64 (f32 external output)
    p.seg[3] = { sh, wtp, bp, sent_out,  768,  1, EMB,     0, 0, 3648 };

    gemm_f16<<<3712, 512, SMEM_TOTAL>>>(p);

    epilogue_kernel<<<BS, 256>>>(words_out, word_vec);
}